// round 1
// baseline (speedup 1.0000x reference)
#include <cuda_runtime.h>

#define NN   128
#define FIN  512
#define EE   128
#define H1D  256
#define H2D  128
#define MAXC 8
#define TPB  1024

// ---------------- persistent device state (rewritten every launch) ----------
__device__ float g_P[NN*EE];       // feature_origin @ W_e   (no bias, no relu)
__device__ float g_feat0[NN*EE];   // relu(P + b_e)
__device__ float g_G0[NN*H1D];     // feat0 @ W1_bot
__device__ float g_G[NN*H1D];      // current feature @ W1_bot
__device__ float g_feat[NN*EE];    // current feature
__device__ int   g_cand[NN*MAXC];
__device__ int   g_ccnt[NN];
__device__ int   g_upd[NN];

// ---------------- init A: P, feat0, feature, updated, candidate lists -------
__global__ void initA_kernel(const float* __restrict__ fo, const float* __restrict__ We,
                             const float* __restrict__ be, const float* __restrict__ adj)
{
    int i = blockIdx.x, e = threadIdx.x;
    float s = 0.f;
    #pragma unroll 4
    for (int f = 0; f < FIN; f++) s += fo[i*FIN+f] * We[f*EE+e];
    g_P[i*EE+e] = s;
    float f0 = fmaxf(s + be[e], 0.f);
    g_feat0[i*EE+e] = f0;
    g_feat [i*EE+e] = f0;
    if (e == 0) {
        g_upd[i] = 0;
        int c = 0;
        for (int v = 0; v < NN; v++)
            if (adj[i*NN+v] != 0.0f) { if (c < MAXC) g_cand[i*MAXC+c] = v; c++; }
        if (c > 3) c = 3;            // K=3 => <=3 distinct candidates per row
        g_ccnt[i] = c;
    }
}

// ---------------- init B: G0 = feat0 @ W1_bot ; G = G0 ----------------------
__global__ void initB_kernel(const float* __restrict__ W1)
{
    int i = blockIdx.x, j = threadIdx.x;   // 128 x 256
    float s = 0.f;
    #pragma unroll 4
    for (int k = 0; k < EE; k++) s += g_feat0[i*EE+k] * W1[(EE+k)*H1D + j];
    g_G0[i*H1D+j] = s;
    g_G [i*H1D+j] = s;
}

// ---------------- main sequential rollout: ONE CTA --------------------------
extern __shared__ float sm[];

__global__ void __launch_bounds__(TPB, 1) main_kernel(
    const float* __restrict__ W1, const float* __restrict__ W2,
    const float* __restrict__ b1, const float* __restrict__ b2,
    const float* __restrict__ wlk, const float* __restrict__ blk,
    const float* __restrict__ wact, const float* __restrict__ bact,
    const float* __restrict__ be)
{
    // smem layout (floats)
    float* W2s  = sm;                  // 32768 : W2 [256][128]
    float* h1T  = W2s + H1D*H2D;       // 1024  : h1 transposed [k][4 rows]
    float* part = h1T + H1D*4;         // 4096  : S2 partials [8w][4r][128j]
    float* hid  = part + 8*4*H2D;      // 512   : hidden [4][128]
    float* dual = hid + 4*H2D;         // 512   : matvec partials [2][256]
    float* a_   = dual + 512;          // 256   : a = x_i @ W1_top
    float* curx = a_ + H1D;            // 128
    float* selP = curx + EE;           // 128
    float* b1s  = selP + EE;           // 256
    float* b2s  = b1s + H1D;           // 128
    float* wlks = b2s + H2D;           // 128
    float* wa0  = wlks + H2D;          // 128
    float* wa1  = wa0 + H2D;           // 128
    float* bes  = wa1 + H2D;           // 128

    __shared__ float s_lk[4], s_a0[4], s_a1[4];
    __shared__ float s_cnt, s_denom, s_blk, s_ba0, s_ba1;
    __shared__ int   s_alive[MAXC];
    __shared__ int   s_na, s_vsel, s_at, s_done, s_needgi, s_gdirty;

    const int tid  = threadIdx.x;
    const int w    = tid >> 5;
    const int lane = tid & 31;

    for (int t = tid; t < H1D*H2D; t += TPB) W2s[t] = W2[t];
    if (tid < H1D) b1s[tid] = b1[tid];
    if (tid < H2D) { b2s[tid] = b2[tid]; wlks[tid] = wlk[tid];
                     wa0[tid] = wact[tid*2]; wa1[tid] = wact[tid*2+1]; }
    if (tid < EE)  bes[tid] = be[tid];
    if (tid == 0)  { s_blk = blk[0]; s_ba0 = bact[0]; s_ba1 = bact[1]; }
    __syncthreads();

    for (int i = 0; i < NN; i++) {
        // -------- node init --------
        if (tid < EE) { curx[tid] = g_feat[i*EE+tid]; selP[tid] = 0.f; }
        if (tid == 0) {
            int c = g_ccnt[i]; s_na = c;
            for (int q = 0; q < c; q++) s_alive[q] = g_cand[i*MAXC+q];
            s_cnt = 0.f; s_done = 0; s_gdirty = 0;
        }
        __syncthreads();

        // a = curx @ W1_top  (warps 0..15, k split in halves)
        if (w < 16) {
            int h = w >> 3;
            int j = ((w & 7) << 5) | lane;
            float s = 0.f;
            const float* base = W1 + (h*64)*H1D + j;
            #pragma unroll 8
            for (int k = 0; k < 64; k++) s += curx[h*64+k] * base[k*H1D];
            dual[h*256+j] = s;
        }
        __syncthreads();
        if (tid < H1D) a_[tid] = dual[tid] + dual[256+tid];
        __syncthreads();

        // -------- step loop (MAX_STEPS = 4, early break on sentinel) --------
        for (int step = 0; step < 4; step++) {
            int na    = s_na;
            int nrows = na + 1;          // candidates + sentinel

            // S1: h1 rows (coalesced G reads), packed as h1T[k][r]
            {
                int r = tid >> 8;        // 0..3
                int k = tid & 255;       // 0..255
                float val = 0.f;
                if (r < nrows) {
                    float g = 0.f;
                    if (r < na) {
                        int v = s_alive[r];
                        if (v > 0) g = g_G[v*H1D + k];   // `if v > 0` quirk
                    }
                    val = fmaxf(a_[k] + g + b1s[k], 0.f);
                }
                h1T[k*4 + r] = val;
            }
            __syncthreads();

            // S2: hidden = relu(h1 @ W2 + b2), 4-row register blocking,
            //     warps 0..7 each own a 32-wide k slab
            if (w < 8) {
                float a00=0,a01=0,a02=0,a03=0, a10=0,a11=0,a12=0,a13=0;
                float a20=0,a21=0,a22=0,a23=0, a30=0,a31=0,a32=0,a33=0;
                int kk = w * 32;
                #pragma unroll 8
                for (int k = kk; k < kk+32; k++) {
                    float4 h4 = *(const float4*)(h1T + 4*k);
                    float4 w4 = *(const float4*)(W2s + k*H2D + lane*4);
                    a00+=h4.x*w4.x; a01+=h4.x*w4.y; a02+=h4.x*w4.z; a03+=h4.x*w4.w;
                    a10+=h4.y*w4.x; a11+=h4.y*w4.y; a12+=h4.y*w4.z; a13+=h4.y*w4.w;
                    a20+=h4.z*w4.x; a21+=h4.z*w4.y; a22+=h4.z*w4.z; a23+=h4.z*w4.w;
                    a30+=h4.w*w4.x; a31+=h4.w*w4.y; a32+=h4.w*w4.z; a33+=h4.w*w4.w;
                }
                float* p = part + (w*4)*H2D + lane*4;
                p[0]=a00; p[1]=a01; p[2]=a02; p[3]=a03; p += H2D;
                p[0]=a10; p[1]=a11; p[2]=a12; p[3]=a13; p += H2D;
                p[0]=a20; p[1]=a21; p[2]=a22; p[3]=a23; p += H2D;
                p[0]=a30; p[1]=a31; p[2]=a32; p[3]=a33;
            }
            __syncthreads();
            if (tid < 512) {
                int r = tid >> 7, j = tid & 127;
                float s = 0.f;
                #pragma unroll
                for (int q = 0; q < 8; q++) s += part[(q*4+r)*H2D + j];
                hid[r*H2D + j] = fmaxf(s + b2s[j], 0.f);
            }
            __syncthreads();

            // S3: per-row lk / act dots (warp r handles row r)
            if (w < 4) {
                float lk = 0.f, p0 = 0.f, p1 = 0.f;
                #pragma unroll
                for (int c = 0; c < 4; c++) {
                    int j = lane*4 + c;
                    float h = hid[w*H2D + j];
                    lk += h*wlks[j]; p0 += h*wa0[j]; p1 += h*wa1[j];
                }
                #pragma unroll
                for (int off = 16; off; off >>= 1) {
                    lk += __shfl_xor_sync(0xffffffffu, lk, off);
                    p0 += __shfl_xor_sync(0xffffffffu, p0, off);
                    p1 += __shfl_xor_sync(0xffffffffu, p1, off);
                }
                if (lane == 0) { s_lk[w] = lk + s_blk; s_a0[w] = p0 + s_ba0; s_a1[w] = p1 + s_ba1; }
            }
            __syncthreads();

            // S4a: argmax decision (first-of-max: ascending candidates, sentinel last)
            if (tid == 0) {
                float best = -3.4028235e38f; int bi = -1;
                for (int r = 0; r < na; r++)
                    if (s_lk[r] > best) { best = s_lk[r]; bi = r; }
                if (s_lk[na] > best) {
                    s_done = 1;                              // sentinel chosen -> all later steps no-ops
                } else {
                    int v  = s_alive[bi];
                    int at = (s_a1[bi] > s_a0[bi]) ? 1 : 0;  // argmax of 2, tie -> 0
                    s_vsel = v; s_at = at;
                    s_denom = s_cnt + (float)at + 1.0f;      // uses PRE-update cnt
                    s_cnt  += (float)at;
                    for (int q = bi; q < na-1; q++) s_alive[q] = s_alive[q+1];
                    s_na = na - 1;
                    int ng = 0;
                    for (int q = 0; q < na-1; q++) if (s_alive[q] == i) ng = 1;
                    s_needgi = ng;                           // i still a live candidate?
                    s_gdirty = (v == i) ? 0 : 1;
                    g_upd[i] = 1; g_upd[v] = 1;
                }
            }
            __syncthreads();
            if (s_done) break;                               // uniform

            // S4b: apply updates in projected space
            {
                int v = s_vsel; float atf = (float)s_at; float denom = s_denom;
                if (tid < EE) {
                    int e = tid;
                    float pv = g_P[v*EE+e], pi = g_P[i*EE+e];
                    float nx = fmaxf((selP[e] + atf*pv + pi)/denom + bes[e], 0.f);
                    if (s_at) selP[e] += pv;
                    float f0v = g_feat0[v*EE+e];
                    g_feat[v*EE+e] = f0v;                    // .at[utc].set(embed(x_ut))
                    float fx = (v == i) ? f0v : nx;          // utc==i: second write wins
                    g_feat[i*EE+e] = fx;
                    curx[e] = fx;
                } else if (tid < EE + H1D) {
                    int j = tid - EE;
                    g_G[v*H1D + j] = g_G0[v*H1D + j];        // feature[utc]=feat0[utc]
                }
            }
            __syncthreads();

            // S5: refresh a = curx @ W1_top; refresh G[i] only if i is still a candidate
            if (w < 16) {
                int h = w >> 3;
                int j = ((w & 7) << 5) | lane;
                float s = 0.f;
                const float* base = W1 + (h*64)*H1D + j;
                #pragma unroll 8
                for (int k = 0; k < 64; k++) s += curx[h*64+k] * base[k*H1D];
                dual[h*256+j] = s;
            } else if (s_needgi) {
                int h = (w - 16) >> 3;
                int j = (((w - 16) & 7) << 5) | lane;
                float s = 0.f;
                const float* base = W1 + (EE + h*64)*H1D + j;
                #pragma unroll 8
                for (int k = 0; k < 64; k++) s += curx[h*64+k] * base[k*H1D];
                part[h*256+j] = s;
            }
            __syncthreads();
            if (tid < H1D) a_[tid] = dual[tid] + dual[256+tid];
            else if (tid < 2*H1D && s_needgi) {
                int j = tid - H1D;
                g_G[i*H1D + j] = part[j] + part[256+j];
            }
            if (tid == 0 && s_needgi) s_gdirty = 0;
            __syncthreads();
        } // steps

        // node end: lazy G[i] = feature[i] @ W1_bot (once, only if stale)
        if (s_gdirty) {
            if (w < 16) {
                int h = w >> 3;
                int j = ((w & 7) << 5) | lane;
                float s = 0.f;
                const float* base = W1 + (EE + h*64)*H1D + j;
                #pragma unroll 8
                for (int k = 0; k < 64; k++) s += curx[h*64+k] * base[k*H1D];
                dual[h*256+j] = s;
            }
            __syncthreads();
            if (tid < H1D) g_G[i*H1D + tid] = dual[tid] + dual[256+tid];
            __syncthreads();
        }
    } // nodes
}

// ---------------- output: zero untouched rows --------------------------------
__global__ void out_kernel(float* __restrict__ out)
{
    int t = blockIdx.x*blockDim.x + threadIdx.x;
    if (t < NN*EE) out[t] = g_upd[t >> 7] ? g_feat[t] : 0.f;
}

// ---------------- launch ------------------------------------------------------
static const int SMEM_BYTES = (H1D*H2D + H1D*4 + 8*4*H2D + 4*H2D + 512 + H1D
                               + EE + EE + H1D + H2D + H2D + H2D + H2D + EE) * (int)sizeof(float);

extern "C" void kernel_launch(void* const* d_in, const int* in_sizes, int n_in,
                              void* d_out, int out_size)
{
    const float* adj = (const float*)d_in[0];
    const float* fo  = (const float*)d_in[1];
    // d_in[2] = labels (unused)
    const float* We  = (const float*)d_in[3];
    const float* be  = (const float*)d_in[4];
    const float* W1  = (const float*)d_in[5];
    const float* b1  = (const float*)d_in[6];
    const float* W2  = (const float*)d_in[7];
    const float* b2  = (const float*)d_in[8];
    const float* wlk = (const float*)d_in[9];
    const float* blk = (const float*)d_in[10];
    const float* wac = (const float*)d_in[11];
    const float* bac = (const float*)d_in[12];
    float* out = (float*)d_out;

    cudaFuncSetAttribute(main_kernel, cudaFuncAttributeMaxDynamicSharedMemorySize, SMEM_BYTES);

    initA_kernel<<<NN, EE>>>(fo, We, be, adj);
    initB_kernel<<<NN, H1D>>>(W1);
    main_kernel<<<1, TPB, SMEM_BYTES>>>(W1, W2, b1, b2, wlk, blk, wac, bac, be);
    out_kernel<<<32, 512>>>(out);
}

// round 2
// speedup vs baseline: 1.7949x; 1.7949x over previous
#include <cuda_runtime.h>

#define NN   128
#define FIN  512
#define EE   128
#define H1D  256
#define H2D  128
#define MAXC 8
#define TPB  512

typedef unsigned long long ull;

__device__ __forceinline__ ull ffma2(ull a, ull b, ull c){
    ull d;
    asm("fma.rn.f32x2 %0, %1, %2, %3;" : "=l"(d) : "l"(a), "l"(b), "l"(c));
    return d;
}
__device__ __forceinline__ ull packff(float x){
    ull d; asm("mov.b64 %0, {%1, %2};" : "=l"(d) : "f"(x), "f"(x)); return d;
}

// ---------------- persistent device state (rewritten every launch) ----------
__device__ float g_P[NN*EE];       // feature_origin @ W_e
__device__ float g_feat0[NN*EE];   // relu(P + b_e)
__device__ float g_A0[NN*H1D];     // feat0 @ W1_top
__device__ float g_G0[NN*H1D];     // feat0 @ W1_bot
__device__ float g_G[NN*H1D];      // current feature @ W1_bot
__device__ float g_feat[NN*EE];    // current feature
__device__ int   g_cand[NN*MAXC];
__device__ int   g_ccnt[NN];
__device__ int   g_upd[NN];

// ---------------- init A --------------------------------------------------
__global__ void initA_kernel(const float* __restrict__ fo, const float* __restrict__ We,
                             const float* __restrict__ be, const float* __restrict__ adj)
{
    int i = blockIdx.x, e = threadIdx.x;
    float s = 0.f;
    #pragma unroll 4
    for (int f = 0; f < FIN; f++) s += fo[i*FIN+f] * We[f*EE+e];
    g_P[i*EE+e] = s;
    float f0 = fmaxf(s + be[e], 0.f);
    g_feat0[i*EE+e] = f0;
    g_feat [i*EE+e] = f0;
    if (e == 0) {
        g_upd[i] = 0;
        int c = 0;
        for (int v = 0; v < NN; v++)
            if (adj[i*NN+v] != 0.0f) { if (c < MAXC) g_cand[i*MAXC+c] = v; c++; }
        if (c > 3) c = 3;
        g_ccnt[i] = c;
    }
}

// ---------------- init B: A0/G0/G -----------------------------------------
__global__ void initB_kernel(const float* __restrict__ W1)
{
    int i = blockIdx.x, j = threadIdx.x;   // 128 x 256
    float st = 0.f, sb = 0.f;
    #pragma unroll 4
    for (int k = 0; k < EE; k++){
        float f = g_feat0[i*EE+k];
        st += f * W1[k*H1D + j];
        sb += f * W1[(EE+k)*H1D + j];
    }
    g_A0[i*H1D+j] = st;
    g_G0[i*H1D+j] = sb;
    g_G [i*H1D+j] = sb;
}

// ---------------- main sequential rollout: ONE CTA, 512 threads -----------
__global__ void __launch_bounds__(TPB, 1) main_kernel(
    const float* __restrict__ W1, const float* __restrict__ W2,
    const float* __restrict__ b1, const float* __restrict__ b2,
    const float* __restrict__ wlk, const float* __restrict__ blk,
    const float* __restrict__ wact, const float* __restrict__ bact,
    const float* __restrict__ be, float* __restrict__ out)
{
    __shared__ __align__(16) float a_[H1D];
    __shared__ __align__(16) float dual[8*H1D];
    __shared__ __align__(16) float h1T[H1D*4];
    __shared__ __align__(16) float2 part01[8*H2D];   // also reused as dualB (2048 floats)
    __shared__ __align__(16) float2 part23[8*H2D];
    __shared__ float curx[EE], selP[EE];
    __shared__ float b1s[H1D], b2s[H2D], wlks[H2D], wa0[H2D], wa1[H2D], bes[EE];
    __shared__ float s_lk[4], s_a0[4], s_a1[4];
    __shared__ float s_cnt, s_denom, s_blk, s_ba0, s_ba1;
    __shared__ int   s_alive[MAXC];
    __shared__ int   s_na, s_vsel, s_at, s_done, s_needgi, s_gdirty;

    const int tid  = threadIdx.x;
    const int w    = tid >> 5;
    const int lane = tid & 31;
    const int kslab = w >> 1, jh = w & 1;
    const int j0 = jh*64 + lane*2;

    if (tid < H1D) b1s[tid] = b1[tid];
    if (tid < H2D) { b2s[tid]=b2[tid]; wlks[tid]=wlk[tid];
                     wa0[tid]=wact[tid*2]; wa1[tid]=wact[tid*2+1]; }
    if (tid < EE)  bes[tid] = be[tid];
    if (tid == 0)  { s_blk=blk[0]; s_ba0=bact[0]; s_ba1=bact[1]; }

    // W2 register-resident: thread owns columns (j0, j0+1) for its 32-k slab
    float w2a[32], w2b[32];
    #pragma unroll
    for (int kk = 0; kk < 32; kk++){
        float2 v = *(const float2*)(W2 + (kslab*32+kk)*H2D + j0);
        w2a[kk] = v.x; w2b[kk] = v.y;
    }
    __syncthreads();

    for (int i = 0; i < NN; i++) {
        // node init: feature[i] == feat0[i] provably => a = A0[i]
        if (tid < H1D) a_[tid] = g_A0[i*H1D+tid];
        if (tid < EE)  { curx[tid] = g_feat[i*EE+tid]; selP[tid] = 0.f; }
        if (tid == 0) {
            int c = g_ccnt[i]; s_na = c;
            for (int q = 0; q < c; q++) s_alive[q] = g_cand[i*MAXC+q];
            s_cnt = 0.f; s_done = 0; s_gdirty = 0;
        }
        __syncthreads();

        for (int step = 0; step < 3; step++) {
            int na = s_na;
            if (na == 0) break;            // next step is forced sentinel
            int nrows = na + 1;

            // S1: h1T[k][r] = relu(a_k + G_vr_k + b1_k)
            {
                int k = tid & 255, rp = tid >> 8;
                float ak = a_[k] + b1s[k];
                #pragma unroll
                for (int rr = 0; rr < 2; rr++){
                    int r = rp*2 + rr;
                    float val = 0.f;
                    if (r < na) { int v = s_alive[r];
                                  float g = (v > 0) ? g_G[v*H1D+k] : 0.f;   // `if v>0` quirk
                                  val = fmaxf(ak + g, 0.f); }
                    else if (r == na) val = fmaxf(ak, 0.f);                  // sentinel
                    h1T[k*4+r] = val;
                }
            }
            __syncthreads();

            // S2: z[r][j] partials, packed f32x2 over row-pairs, W2 in regs
            if (nrows > 2) {
                ull a01a=0, a23a=0, a01b=0, a23b=0;
                #pragma unroll
                for (int kk = 0; kk < 32; kk++){
                    int k = kslab*32 + kk;
                    ulonglong2 hp = *(const ulonglong2*)(h1T + 4*k);
                    ull wpa = packff(w2a[kk]), wpb = packff(w2b[kk]);
                    a01a = ffma2(hp.x, wpa, a01a);
                    a23a = ffma2(hp.y, wpa, a23a);
                    a01b = ffma2(hp.x, wpb, a01b);
                    a23b = ffma2(hp.y, wpb, a23b);
                }
                part01[kslab*H2D+j0]   = *(float2*)&a01a;
                part01[kslab*H2D+j0+1] = *(float2*)&a01b;
                part23[kslab*H2D+j0]   = *(float2*)&a23a;
                part23[kslab*H2D+j0+1] = *(float2*)&a23b;
            } else {
                ull a01a=0, a01b=0;
                #pragma unroll
                for (int kk = 0; kk < 32; kk++){
                    int k = kslab*32 + kk;
                    ull hx = *(const ull*)(h1T + 4*k);
                    ull wpa = packff(w2a[kk]), wpb = packff(w2b[kk]);
                    a01a = ffma2(hx, wpa, a01a);
                    a01b = ffma2(hx, wpb, a01b);
                }
                part01[kslab*H2D+j0]   = *(float2*)&a01a;
                part01[kslab*H2D+j0+1] = *(float2*)&a01b;
            }
            __syncthreads();

            // S3: relu + 3 dots per row (warp r handles row r), reads partials
            if (w < nrows) {
                const float2* pr = (w < 2) ? part01 : part23;
                int hi = w & 1;
                float lk = 0.f, p0 = 0.f, p1 = 0.f;
                #pragma unroll
                for (int q = 0; q < 4; q++){
                    int j = lane + q*32;
                    float s = b2s[j];
                    #pragma unroll
                    for (int ks = 0; ks < 8; ks++){
                        float2 v = pr[ks*H2D + j];
                        s += hi ? v.y : v.x;
                    }
                    float h = fmaxf(s, 0.f);
                    lk += h*wlks[j]; p0 += h*wa0[j]; p1 += h*wa1[j];
                }
                #pragma unroll
                for (int off = 16; off; off >>= 1){
                    lk += __shfl_xor_sync(0xffffffffu, lk, off);
                    p0 += __shfl_xor_sync(0xffffffffu, p0, off);
                    p1 += __shfl_xor_sync(0xffffffffu, p1, off);
                }
                if (lane == 0){ s_lk[w]=lk+s_blk; s_a0[w]=p0+s_ba0; s_a1[w]=p1+s_ba1; }
            }
            __syncthreads();

            // S4a: argmax decision (first-of-max; sentinel last, strict >)
            if (tid == 0) {
                float best = -3.4028235e38f; int bi = -1;
                for (int r = 0; r < na; r++)
                    if (s_lk[r] > best) { best = s_lk[r]; bi = r; }
                if (s_lk[na] > best) {
                    s_done = 1;
                } else {
                    int v  = s_alive[bi];
                    int at = (s_a1[bi] > s_a0[bi]) ? 1 : 0;
                    s_vsel = v; s_at = at;
                    s_denom = s_cnt + (float)at + 1.0f;
                    s_cnt  += (float)at;
                    for (int q = bi; q < na-1; q++) s_alive[q] = s_alive[q+1];
                    s_na = na - 1;
                    int ng = 0;
                    for (int q = 0; q < na-1; q++) if (s_alive[q] == i) ng = 1;
                    s_needgi = ng;
                    s_gdirty = (v == i) ? 0 : 1;
                    g_upd[i] = 1; g_upd[v] = 1;
                }
            }
            __syncthreads();
            if (s_done) break;

            // S4b: apply updates in projected space
            {
                int v = s_vsel; float atf = (float)s_at; float denom = s_denom;
                if (tid < EE) {
                    int e = tid;
                    float pv = g_P[v*EE+e], pi = g_P[i*EE+e];
                    float nx = fmaxf((selP[e] + atf*pv + pi)/denom + bes[e], 0.f);
                    if (s_at) selP[e] += pv;
                    float f0v = g_feat0[v*EE+e];
                    g_feat[v*EE+e] = f0v;
                    float fx = (v == i) ? f0v : nx;
                    g_feat[i*EE+e] = fx;
                    curx[e] = fx;
                } else if (tid < EE + H1D) {
                    int jj = tid - EE;
                    g_G[v*H1D + jj] = g_G0[v*H1D + jj];
                }
            }
            __syncthreads();
            if (s_na == 0) break;          // no more decisions possible: skip S5

            // S5: a = curx @ W1_top (LDG.128, L1-resident W1_top); + G[i] if needed
            {
                int jg = tid & 63, ks = tid >> 6;
                const float* base = W1 + (ks*16)*H1D + jg*4;
                float4 acc = make_float4(0.f,0.f,0.f,0.f);
                #pragma unroll
                for (int kk = 0; kk < 16; kk++){
                    float4 wr = *(const float4*)(base + kk*H1D);
                    float c = curx[ks*16+kk];
                    acc.x += c*wr.x; acc.y += c*wr.y; acc.z += c*wr.z; acc.w += c*wr.w;
                }
                *(float4*)(dual + ks*H1D + jg*4) = acc;
                if (s_needgi) {
                    float* dualB = (float*)part01;
                    const float* baseB = W1 + (EE + ks*16)*H1D + jg*4;
                    float4 ab = make_float4(0.f,0.f,0.f,0.f);
                    #pragma unroll
                    for (int kk = 0; kk < 16; kk++){
                        float4 wr = *(const float4*)(baseB + kk*H1D);
                        float c = curx[ks*16+kk];
                        ab.x += c*wr.x; ab.y += c*wr.y; ab.z += c*wr.z; ab.w += c*wr.w;
                    }
                    *(float4*)(dualB + ks*H1D + jg*4) = ab;
                }
            }
            __syncthreads();
            if (tid < H1D){
                float s = 0.f;
                #pragma unroll
                for (int ks = 0; ks < 8; ks++) s += dual[ks*H1D+tid];
                a_[tid] = s;
                if (s_needgi){
                    const float* dualB = (const float*)part01;
                    float sb = 0.f;
                    #pragma unroll
                    for (int ks = 0; ks < 8; ks++) sb += dualB[ks*H1D+tid];
                    g_G[i*H1D+tid] = sb;
                }
            }
            if (tid == 0 && s_needgi) s_gdirty = 0;
            __syncthreads();
        } // steps

        // node end: lazy G[i] = feature[i] @ W1_bot (only if stale)
        if (s_gdirty) {
            {
                int jg = tid & 63, ks = tid >> 6;
                const float* baseB = W1 + (EE + ks*16)*H1D + jg*4;
                float4 acc = make_float4(0.f,0.f,0.f,0.f);
                #pragma unroll
                for (int kk = 0; kk < 16; kk++){
                    float4 wr = *(const float4*)(baseB + kk*H1D);
                    float c = curx[ks*16+kk];
                    acc.x += c*wr.x; acc.y += c*wr.y; acc.z += c*wr.z; acc.w += c*wr.w;
                }
                *(float4*)(dual + ks*H1D + jg*4) = acc;
            }
            __syncthreads();
            if (tid < H1D){
                float s = 0.f;
                #pragma unroll
                for (int ks = 0; ks < 8; ks++) s += dual[ks*H1D+tid];
                g_G[i*H1D+tid] = s;
            }
            __syncthreads();
        }
    } // nodes

    // output: zero untouched rows (folded in; saves a launch)
    __syncthreads();
    for (int t = tid; t < NN*EE; t += TPB)
        out[t] = g_upd[t >> 7] ? g_feat[t] : 0.f;
}

// ---------------- launch ---------------------------------------------------
extern "C" void kernel_launch(void* const* d_in, const int* in_sizes, int n_in,
                              void* d_out, int out_size)
{
    const float* adj = (const float*)d_in[0];
    const float* fo  = (const float*)d_in[1];
    // d_in[2] = labels (unused)
    const float* We  = (const float*)d_in[3];
    const float* be  = (const float*)d_in[4];
    const float* W1  = (const float*)d_in[5];
    const float* b1  = (const float*)d_in[6];
    const float* W2  = (const float*)d_in[7];
    const float* b2  = (const float*)d_in[8];
    const float* wlk = (const float*)d_in[9];
    const float* blk = (const float*)d_in[10];
    const float* wac = (const float*)d_in[11];
    const float* bac = (const float*)d_in[12];
    float* out = (float*)d_out;

    initA_kernel<<<NN, EE>>>(fo, We, be, adj);
    initB_kernel<<<NN, H1D>>>(W1);
    main_kernel<<<1, TPB>>>(W1, W2, b1, b2, wlk, blk, wac, bac, be, out);
}

// round 3
// speedup vs baseline: 1.7957x; 1.0004x over previous
#include <cuda_runtime.h>

#define NN   128
#define FIN  512
#define EE   128
#define H1D  256
#define H2D  128
#define MAXC 8
#define TPB  512

typedef unsigned long long ull;

__device__ __forceinline__ ull ffma2(ull a, ull b, ull c){
    ull d;
    asm("fma.rn.f32x2 %0, %1, %2, %3;" : "=l"(d) : "l"(a), "l"(b), "l"(c));
    return d;
}
__device__ __forceinline__ ull packff(float x){
    ull d; asm("mov.b64 %0, {%1, %2};" : "=l"(d) : "f"(x), "f"(x)); return d;
}

// ---------------- persistent device state (rewritten every launch) ----------
__device__ float g_P[NN*EE];       // feature_origin @ W_e
__device__ float g_feat0[NN*EE];   // relu(P + b_e)
__device__ float g_A0[NN*H1D];     // feat0 @ W1_top
__device__ float g_G0[NN*H1D];     // feat0 @ W1_bot
__device__ float g_G[NN*H1D];      // current feature @ W1_bot
__device__ float g_feat[NN*EE];    // current feature
__device__ int   g_cand[NN*MAXC];
__device__ int   g_ccnt[NN];
__device__ int   g_upd[NN];

// ---------------- init A --------------------------------------------------
__global__ void initA_kernel(const float* __restrict__ fo, const float* __restrict__ We,
                             const float* __restrict__ be, const float* __restrict__ adj)
{
    int i = blockIdx.x, e = threadIdx.x;
    float s = 0.f;
    #pragma unroll 4
    for (int f = 0; f < FIN; f++) s += fo[i*FIN+f] * We[f*EE+e];
    g_P[i*EE+e] = s;
    float f0 = fmaxf(s + be[e], 0.f);
    g_feat0[i*EE+e] = f0;
    g_feat [i*EE+e] = f0;
    if (e == 0) {
        g_upd[i] = 0;
        int c = 0;
        for (int v = 0; v < NN; v++)
            if (adj[i*NN+v] != 0.0f) { if (c < MAXC) g_cand[i*MAXC+c] = v; c++; }
        if (c > 3) c = 3;
        g_ccnt[i] = c;
    }
}

// ---------------- init B: A0/G0/G -----------------------------------------
__global__ void initB_kernel(const float* __restrict__ W1)
{
    int i = blockIdx.x, j = threadIdx.x;   // 128 x 256
    float st = 0.f, sb = 0.f;
    #pragma unroll 4
    for (int k = 0; k < EE; k++){
        float f = g_feat0[i*EE+k];
        st += f * W1[k*H1D + j];
        sb += f * W1[(EE+k)*H1D + j];
    }
    g_A0[i*H1D+j] = st;
    g_G0[i*H1D+j] = sb;
    g_G [i*H1D+j] = sb;
}

// ---------------- main sequential rollout: ONE CTA, 512 threads -----------
__global__ void __launch_bounds__(TPB, 1) main_kernel(
    const float* __restrict__ W1, const float* __restrict__ W2,
    const float* __restrict__ b1, const float* __restrict__ b2,
    const float* __restrict__ wlk, const float* __restrict__ blk,
    const float* __restrict__ wact, const float* __restrict__ bact,
    const float* __restrict__ be, float* __restrict__ out)
{
    __shared__ __align__(16) float a_[H1D];
    __shared__ __align__(16) float dual[8*H1D];
    __shared__ __align__(16) float h1T[H1D*4];
    __shared__ __align__(16) float2 part01[8*H2D];   // also reused as dualB (2048 floats)
    __shared__ __align__(16) float2 part23[8*H2D];
    __shared__ float curx[EE], selP[EE];
    __shared__ float b1s[H1D], b2s[H2D], wlks[H2D], wa0[H2D], wa1[H2D], bes[EE];
    __shared__ float s_lk[4], s_a0[4], s_a1[4];
    __shared__ float s_cnt, s_denom, s_blk, s_ba0, s_ba1;
    __shared__ int   s_alive[MAXC];
    __shared__ int   s_na, s_vsel, s_at, s_done, s_needgi, s_gdirty;

    const int tid  = threadIdx.x;
    const int w    = tid >> 5;
    const int lane = tid & 31;
    const int kslab = w >> 1, jh = w & 1;
    const int j0 = jh*64 + lane*2;

    if (tid < H1D) b1s[tid] = b1[tid];
    if (tid < H2D) { b2s[tid]=b2[tid]; wlks[tid]=wlk[tid];
                     wa0[tid]=wact[tid*2]; wa1[tid]=wact[tid*2+1]; }
    if (tid < EE)  bes[tid] = be[tid];
    if (tid == 0)  { s_blk=blk[0]; s_ba0=bact[0]; s_ba1=bact[1]; }

    // W2 register-resident: thread owns columns (j0, j0+1) for its 32-k slab
    float w2a[32], w2b[32];
    #pragma unroll
    for (int kk = 0; kk < 32; kk++){
        float2 v = *(const float2*)(W2 + (kslab*32+kk)*H2D + j0);
        w2a[kk] = v.x; w2b[kk] = v.y;
    }
    __syncthreads();

    for (int i = 0; i < NN; i++) {
        // node init: feature[i] == feat0[i] provably => a = A0[i]
        if (tid < H1D) a_[tid] = g_A0[i*H1D+tid];
        if (tid < EE)  { curx[tid] = g_feat[i*EE+tid]; selP[tid] = 0.f; }
        if (tid == 0) {
            int c = g_ccnt[i]; s_na = c;
            for (int q = 0; q < c; q++) s_alive[q] = g_cand[i*MAXC+q];
            s_cnt = 0.f; s_done = 0; s_gdirty = 0;
        }
        __syncthreads();

        for (int step = 0; step < 3; step++) {
            int na = s_na;
            if (na == 0) break;            // next step is forced sentinel
            int nrows = na + 1;

            // S1: h1T[k][r] = relu(a_k + G_vr_k + b1_k)
            {
                int k = tid & 255, rp = tid >> 8;
                float ak = a_[k] + b1s[k];
                #pragma unroll
                for (int rr = 0; rr < 2; rr++){
                    int r = rp*2 + rr;
                    float val = 0.f;
                    if (r < na) { int v = s_alive[r];
                                  float g = (v > 0) ? g_G[v*H1D+k] : 0.f;   // `if v>0` quirk
                                  val = fmaxf(ak + g, 0.f); }
                    else if (r == na) val = fmaxf(ak, 0.f);                  // sentinel
                    h1T[k*4+r] = val;
                }
            }
            __syncthreads();

            // S2: z[r][j] partials, packed f32x2 over row-pairs, W2 in regs
            if (nrows > 2) {
                ull a01a=0, a23a=0, a01b=0, a23b=0;
                #pragma unroll
                for (int kk = 0; kk < 32; kk++){
                    int k = kslab*32 + kk;
                    ulonglong2 hp = *(const ulonglong2*)(h1T + 4*k);
                    ull wpa = packff(w2a[kk]), wpb = packff(w2b[kk]);
                    a01a = ffma2(hp.x, wpa, a01a);
                    a23a = ffma2(hp.y, wpa, a23a);
                    a01b = ffma2(hp.x, wpb, a01b);
                    a23b = ffma2(hp.y, wpb, a23b);
                }
                part01[kslab*H2D+j0]   = *(float2*)&a01a;
                part01[kslab*H2D+j0+1] = *(float2*)&a01b;
                part23[kslab*H2D+j0]   = *(float2*)&a23a;
                part23[kslab*H2D+j0+1] = *(float2*)&a23b;
            } else {
                ull a01a=0, a01b=0;
                #pragma unroll
                for (int kk = 0; kk < 32; kk++){
                    int k = kslab*32 + kk;
                    ull hx = *(const ull*)(h1T + 4*k);
                    ull wpa = packff(w2a[kk]), wpb = packff(w2b[kk]);
                    a01a = ffma2(hx, wpa, a01a);
                    a01b = ffma2(hx, wpb, a01b);
                }
                part01[kslab*H2D+j0]   = *(float2*)&a01a;
                part01[kslab*H2D+j0+1] = *(float2*)&a01b;
            }
            __syncthreads();

            // S3: relu + 3 dots per row (warp r handles row r), reads partials
            if (w < nrows) {
                const float2* pr = (w < 2) ? part01 : part23;
                int hi = w & 1;
                float lk = 0.f, p0 = 0.f, p1 = 0.f;
                #pragma unroll
                for (int q = 0; q < 4; q++){
                    int j = lane + q*32;
                    float s = b2s[j];
                    #pragma unroll
                    for (int ks = 0; ks < 8; ks++){
                        float2 v = pr[ks*H2D + j];
                        s += hi ? v.y : v.x;
                    }
                    float h = fmaxf(s, 0.f);
                    lk += h*wlks[j]; p0 += h*wa0[j]; p1 += h*wa1[j];
                }
                #pragma unroll
                for (int off = 16; off; off >>= 1){
                    lk += __shfl_xor_sync(0xffffffffu, lk, off);
                    p0 += __shfl_xor_sync(0xffffffffu, p0, off);
                    p1 += __shfl_xor_sync(0xffffffffu, p1, off);
                }
                if (lane == 0){ s_lk[w]=lk+s_blk; s_a0[w]=p0+s_ba0; s_a1[w]=p1+s_ba1; }
            }
            __syncthreads();

            // S4a: argmax decision (first-of-max; sentinel last, strict >)
            if (tid == 0) {
                float best = -3.4028235e38f; int bi = -1;
                for (int r = 0; r < na; r++)
                    if (s_lk[r] > best) { best = s_lk[r]; bi = r; }
                if (s_lk[na] > best) {
                    s_done = 1;
                } else {
                    int v  = s_alive[bi];
                    int at = (s_a1[bi] > s_a0[bi]) ? 1 : 0;
                    s_vsel = v; s_at = at;
                    s_denom = s_cnt + (float)at + 1.0f;
                    s_cnt  += (float)at;
                    for (int q = bi; q < na-1; q++) s_alive[q] = s_alive[q+1];
                    s_na = na - 1;
                    int ng = 0;
                    for (int q = 0; q < na-1; q++) if (s_alive[q] == i) ng = 1;
                    s_needgi = ng;
                    s_gdirty = (v == i) ? 0 : 1;
                    g_upd[i] = 1; g_upd[v] = 1;
                }
            }
            __syncthreads();
            if (s_done) break;

            // S4b: apply updates in projected space
            {
                int v = s_vsel; float atf = (float)s_at; float denom = s_denom;
                if (tid < EE) {
                    int e = tid;
                    float pv = g_P[v*EE+e], pi = g_P[i*EE+e];
                    float nx = fmaxf((selP[e] + atf*pv + pi)/denom + bes[e], 0.f);
                    if (s_at) selP[e] += pv;
                    float f0v = g_feat0[v*EE+e];
                    g_feat[v*EE+e] = f0v;
                    float fx = (v == i) ? f0v : nx;
                    g_feat[i*EE+e] = fx;
                    curx[e] = fx;
                } else if (tid < EE + H1D) {
                    int jj = tid - EE;
                    g_G[v*H1D + jj] = g_G0[v*H1D + jj];
                }
            }
            __syncthreads();
            if (s_na == 0) break;          // no more decisions possible: skip S5

            // S5: a = curx @ W1_top (LDG.128, L1-resident W1_top); + G[i] if needed
            {
                int jg = tid & 63, ks = tid >> 6;
                const float* base = W1 + (ks*16)*H1D + jg*4;
                float4 acc = make_float4(0.f,0.f,0.f,0.f);
                #pragma unroll
                for (int kk = 0; kk < 16; kk++){
                    float4 wr = *(const float4*)(base + kk*H1D);
                    float c = curx[ks*16+kk];
                    acc.x += c*wr.x; acc.y += c*wr.y; acc.z += c*wr.z; acc.w += c*wr.w;
                }
                *(float4*)(dual + ks*H1D + jg*4) = acc;
                if (s_needgi) {
                    float* dualB = (float*)part01;
                    const float* baseB = W1 + (EE + ks*16)*H1D + jg*4;
                    float4 ab = make_float4(0.f,0.f,0.f,0.f);
                    #pragma unroll
                    for (int kk = 0; kk < 16; kk++){
                        float4 wr = *(const float4*)(baseB + kk*H1D);
                        float c = curx[ks*16+kk];
                        ab.x += c*wr.x; ab.y += c*wr.y; ab.z += c*wr.z; ab.w += c*wr.w;
                    }
                    *(float4*)(dualB + ks*H1D + jg*4) = ab;
                }
            }
            __syncthreads();
            if (tid < H1D){
                float s = 0.f;
                #pragma unroll
                for (int ks = 0; ks < 8; ks++) s += dual[ks*H1D+tid];
                a_[tid] = s;
                if (s_needgi){
                    const float* dualB = (const float*)part01;
                    float sb = 0.f;
                    #pragma unroll
                    for (int ks = 0; ks < 8; ks++) sb += dualB[ks*H1D+tid];
                    g_G[i*H1D+tid] = sb;
                }
            }
            if (tid == 0 && s_needgi) s_gdirty = 0;
            __syncthreads();
        } // steps

        // node end: lazy G[i] = feature[i] @ W1_bot (only if stale)
        if (s_gdirty) {
            {
                int jg = tid & 63, ks = tid >> 6;
                const float* baseB = W1 + (EE + ks*16)*H1D + jg*4;
                float4 acc = make_float4(0.f,0.f,0.f,0.f);
                #pragma unroll
                for (int kk = 0; kk < 16; kk++){
                    float4 wr = *(const float4*)(baseB + kk*H1D);
                    float c = curx[ks*16+kk];
                    acc.x += c*wr.x; acc.y += c*wr.y; acc.z += c*wr.z; acc.w += c*wr.w;
                }
                *(float4*)(dual + ks*H1D + jg*4) = acc;
            }
            __syncthreads();
            if (tid < H1D){
                float s = 0.f;
                #pragma unroll
                for (int ks = 0; ks < 8; ks++) s += dual[ks*H1D+tid];
                g_G[i*H1D+tid] = s;
            }
            __syncthreads();
        }
    } // nodes

    // output: zero untouched rows (folded in; saves a launch)
    __syncthreads();
    for (int t = tid; t < NN*EE; t += TPB)
        out[t] = g_upd[t >> 7] ? g_feat[t] : 0.f;
}

// ---------------- launch ---------------------------------------------------
extern "C" void kernel_launch(void* const* d_in, const int* in_sizes, int n_in,
                              void* d_out, int out_size)
{
    const float* adj = (const float*)d_in[0];
    const float* fo  = (const float*)d_in[1];
    // d_in[2] = labels (unused)
    const float* We  = (const float*)d_in[3];
    const float* be  = (const float*)d_in[4];
    const float* W1  = (const float*)d_in[5];
    const float* b1  = (const float*)d_in[6];
    const float* W2  = (const float*)d_in[7];
    const float* b2  = (const float*)d_in[8];
    const float* wlk = (const float*)d_in[9];
    const float* blk = (const float*)d_in[10];
    const float* wac = (const float*)d_in[11];
    const float* bac = (const float*)d_in[12];
    float* out = (float*)d_out;

    initA_kernel<<<NN, EE>>>(fo, We, be, adj);
    initB_kernel<<<NN, H1D>>>(W1);
    main_kernel<<<1, TPB>>>(W1, W2, b1, b2, wlk, blk, wac, bac, be, out);
}